// round 1
// baseline (speedup 1.0000x reference)
#include <cuda_runtime.h>
#include <math.h>

// ---------------------------------------------------------------------------
// Problem geometry (fixed by the reference):
//   x:  (32, 3, 512, 512)
//   h1: (32, 4, 256, 256)   conv1(3x3,SAME)+ReLU+avgpool2
//   h2: (32,16, 128, 128)   conv2(3x3,SAME)+ReLU+avgpool2
//   NetVLAD: K=4 clusters, D=16 dims, M=16384 pixels/image
//   out: (32, 7)
// ---------------------------------------------------------------------------

#define NIMG   32
#define NBLK   16          // partial-reduction blocks per image (deterministic tree)
#define M2     16384       // 128*128
#define EPSN   1e-12f

// Scratch (no cudaMalloc allowed) — fully overwritten every launch.
__device__ float g_h1[NIMG * 4 * 256 * 256];     // 33.5 MB
__device__ float g_h2[NIMG * 16 * 128 * 128];    // 33.5 MB
__device__ float g_part[NIMG * NBLK * 68];       // 64 vlad accum + 4 asum per partial

// ---------------------------------------------------------------------------
// Kernel 1: conv1 (3->4, 3x3, pad 1) + ReLU + 2x2 avgpool, fused.
// One thread = one pooled output pixel, all 4 output channels.
// grid (1, 256, 32), block 256  (ox = tid, oy = blockIdx.y, n = blockIdx.z)
// ---------------------------------------------------------------------------
__global__ void conv1_pool_kernel(const float* __restrict__ x,
                                  const float* __restrict__ w,
                                  const float* __restrict__ bias)
{
    __shared__ float sw[108];   // (4,3,3,3)
    __shared__ float sb[4];
    int t = threadIdx.x;
    if (t < 108) sw[t] = w[t];
    if (t < 4)   sb[t] = bias[t];
    __syncthreads();

    int ox = t;                 // 0..255
    int oy = blockIdx.y;        // 0..255
    int n  = blockIdx.z;

    const float* xb = x + n * 3 * 512 * 512;
    int iy0 = 2 * oy - 1;
    int ix0 = 2 * ox - 1;

    // 4x4 input patch per input channel (covers the 2x2 conv positions + halo)
    float p[3][4][4];
#pragma unroll
    for (int ic = 0; ic < 3; ic++) {
#pragma unroll
        for (int dy = 0; dy < 4; dy++) {
            int iy = iy0 + dy;
            bool okY = (iy >= 0) && (iy < 512);
#pragma unroll
            for (int dx = 0; dx < 4; dx++) {
                int ix = ix0 + dx;
                p[ic][dy][dx] = (okY && ix >= 0 && ix < 512)
                              ? __ldg(&xb[ic * 262144 + iy * 512 + ix]) : 0.0f;
            }
        }
    }

    float* ob = g_h1 + n * 4 * 65536 + oy * 256 + ox;
#pragma unroll
    for (int oc = 0; oc < 4; oc++) {
        float s = 0.0f;
#pragma unroll
        for (int py = 0; py < 2; py++) {
#pragma unroll
            for (int px = 0; px < 2; px++) {
                float v = sb[oc];
#pragma unroll
                for (int ic = 0; ic < 3; ic++)
#pragma unroll
                    for (int ky = 0; ky < 3; ky++)
#pragma unroll
                        for (int kx = 0; kx < 3; kx++)
                            v = fmaf(p[ic][py + ky][px + kx],
                                     sw[((oc * 3 + ic) * 3 + ky) * 3 + kx], v);
                s += fmaxf(v, 0.0f);
            }
        }
        ob[oc * 65536] = s * 0.25f;
    }
}

// ---------------------------------------------------------------------------
// Kernel 2: conv2 (4->16, 3x3, pad 1) + ReLU + 2x2 avgpool, fused.
// One thread = one pooled output pixel, all 16 output channels.
// grid (1, 128, 32), block 128
// ---------------------------------------------------------------------------
__global__ void conv2_pool_kernel(const float* __restrict__ w,
                                  const float* __restrict__ bias)
{
    __shared__ float sw[576];   // (16,4,3,3)
    __shared__ float sb[16];
    int t = threadIdx.x;
    for (int i = t; i < 576; i += 128) sw[i] = w[i];
    if (t < 16) sb[t] = bias[t];
    __syncthreads();

    int ox = t;                 // 0..127
    int oy = blockIdx.y;        // 0..127
    int n  = blockIdx.z;

    const float* xb = g_h1 + n * 4 * 65536;
    int iy0 = 2 * oy - 1;
    int ix0 = 2 * ox - 1;

    // accumulators: 16 out channels x 2x2 conv positions (pre-ReLU)
    float acc[16][2][2];
#pragma unroll
    for (int oc = 0; oc < 16; oc++) {
        float b = sb[oc];
        acc[oc][0][0] = b; acc[oc][0][1] = b;
        acc[oc][1][0] = b; acc[oc][1][1] = b;
    }

    for (int ic = 0; ic < 4; ic++) {
        float p[4][4];
#pragma unroll
        for (int dy = 0; dy < 4; dy++) {
            int iy = iy0 + dy;
            bool okY = (iy >= 0) && (iy < 256);
#pragma unroll
            for (int dx = 0; dx < 4; dx++) {
                int ix = ix0 + dx;
                p[dy][dx] = (okY && ix >= 0 && ix < 256)
                          ? __ldg(&xb[ic * 65536 + iy * 256 + ix]) : 0.0f;
            }
        }
#pragma unroll
        for (int oc = 0; oc < 16; oc++) {
            // 9 weights for this (oc, ic) pair — warp-uniform broadcast loads
            float wk[9];
#pragma unroll
            for (int j = 0; j < 9; j++) wk[j] = sw[(oc * 4 + ic) * 9 + j];
#pragma unroll
            for (int py = 0; py < 2; py++)
#pragma unroll
                for (int px = 0; px < 2; px++) {
                    float v = acc[oc][py][px];
#pragma unroll
                    for (int ky = 0; ky < 3; ky++)
#pragma unroll
                        for (int kx = 0; kx < 3; kx++)
                            v = fmaf(p[py + ky][px + kx], wk[ky * 3 + kx], v);
                    acc[oc][py][px] = v;
                }
        }
    }

    float* ob = g_h2 + n * 16 * M2 + oy * 128 + ox;
#pragma unroll
    for (int oc = 0; oc < 16; oc++) {
        float s = fmaxf(acc[oc][0][0], 0.0f) + fmaxf(acc[oc][0][1], 0.0f)
                + fmaxf(acc[oc][1][0], 0.0f) + fmaxf(acc[oc][1][1], 0.0f);
        ob[oc * M2] = s * 0.25f;
    }
}

// ---------------------------------------------------------------------------
// Kernel 3: NetVLAD partial reduction.
// grid = NIMG*NBLK blocks, block = 128 threads. Block (n, bi) reduces its
// 1024-pixel slice into a 68-float partial: [ sum_m a_k * x_c (k*16+c) | sum_m a_k ].
// All reductions are fixed-order (warp shuffle tree + fixed 4-way sum) =>
// bitwise deterministic across graph replays.
// ---------------------------------------------------------------------------
__global__ __launch_bounds__(128) void netvlad_partial_kernel(
    const float* __restrict__ aw,   // (4,16)
    const float* __restrict__ ab)   // (4,)
{
    __shared__ float sw[64];
    __shared__ float sb[4];
    __shared__ float sred[4][68];

    int t = threadIdx.x;
    if (t < 64) sw[t] = aw[t];
    if (t < 4)  sb[t] = ab[t];
    __syncthreads();

    int n  = blockIdx.x >> 4;      // / NBLK
    int bi = blockIdx.x & (NBLK - 1);
    const float* xb = g_h2 + n * 16 * M2;

    float vacc[64];
    float asum[4];
#pragma unroll
    for (int i = 0; i < 64; i++) vacc[i] = 0.0f;
#pragma unroll
    for (int k = 0; k < 4; k++) asum[k] = 0.0f;

    const int per = M2 / NBLK;     // 1024
    int m_end = (bi + 1) * per;
    for (int m = bi * per + t; m < m_end; m += 128) {
        float xv[16];
#pragma unroll
        for (int c = 0; c < 16; c++) xv[c] = xb[c * M2 + m];

        float lg[4];
#pragma unroll
        for (int k = 0; k < 4; k++) {
            float v = sb[k];
#pragma unroll
            for (int c = 0; c < 16; c++) v = fmaf(sw[k * 16 + c], xv[c], v);
            lg[k] = v;
        }
        float mx = fmaxf(fmaxf(lg[0], lg[1]), fmaxf(lg[2], lg[3]));
        float e0 = __expf(lg[0] - mx), e1 = __expf(lg[1] - mx);
        float e2 = __expf(lg[2] - mx), e3 = __expf(lg[3] - mx);
        float inv = 1.0f / (e0 + e1 + e2 + e3);
        float a[4] = { e0 * inv, e1 * inv, e2 * inv, e3 * inv };
#pragma unroll
        for (int k = 0; k < 4; k++) {
            asum[k] += a[k];
#pragma unroll
            for (int c = 0; c < 16; c++)
                vacc[k * 16 + c] = fmaf(a[k], xv[c], vacc[k * 16 + c]);
        }
    }

    // warp-level fixed tree reduction of the 68 accumulators
    int lane = t & 31, wid = t >> 5;
#pragma unroll
    for (int i = 0; i < 64; i++) {
        float v = vacc[i];
#pragma unroll
        for (int o = 16; o > 0; o >>= 1) v += __shfl_down_sync(0xffffffffu, v, o);
        if (lane == 0) sred[wid][i] = v;
    }
#pragma unroll
    for (int k = 0; k < 4; k++) {
        float v = asum[k];
#pragma unroll
        for (int o = 16; o > 0; o >>= 1) v += __shfl_down_sync(0xffffffffu, v, o);
        if (lane == 0) sred[wid][64 + k] = v;
    }
    __syncthreads();

    if (t < 68) {
        float v = sred[0][t] + sred[1][t] + sred[2][t] + sred[3][t];
        g_part[(n * NBLK + bi) * 68 + t] = v;
    }
}

// ---------------------------------------------------------------------------
// Kernel 4: finalize. grid = NIMG, block = 128.
// Sum the NBLK partials (fixed order), subtract asum*centroid, intra-L2-norm
// per cluster, global L2-norm, then the 64->7 linear layer.
// ---------------------------------------------------------------------------
__global__ void finalize_kernel(const float* __restrict__ cent,   // (4,16)
                                const float* __restrict__ lw,     // (7,64)
                                const float* __restrict__ lb,     // (7,)
                                float* __restrict__ out)          // (32,7)
{
    __shared__ float v[68];
    __shared__ float vn[64];
    __shared__ float norms[4];
    __shared__ float gnorm;

    int n = blockIdx.x;
    int t = threadIdx.x;

    if (t < 68) {
        float s = 0.0f;
#pragma unroll
        for (int b = 0; b < NBLK; b++)
            s += g_part[(n * NBLK + b) * 68 + t];
        v[t] = s;
    }
    __syncthreads();

    if (t < 64) {
        int k = t >> 4;
        vn[t] = v[t] - v[64 + k] * cent[t];
    }
    __syncthreads();

    if (t < 4) {
        float s = 0.0f;
#pragma unroll
        for (int c = 0; c < 16; c++) { float q = vn[t * 16 + c]; s += q * q; }
        norms[t] = fmaxf(sqrtf(s), EPSN);
    }
    __syncthreads();

    if (t < 64) vn[t] = vn[t] / norms[t >> 4];
    __syncthreads();

    if (t == 0) {
        float s = 0.0f;
#pragma unroll
        for (int i = 0; i < 64; i++) s += vn[i] * vn[i];
        gnorm = fmaxf(sqrtf(s), EPSN);
    }
    __syncthreads();

    if (t < 7) {
        float g = 1.0f / gnorm;
        float s = lb[t];
#pragma unroll
        for (int i = 0; i < 64; i++) s = fmaf(vn[i] * g, lw[t * 64 + i], s);
        out[n * 7 + t] = s;
    }
}

// ---------------------------------------------------------------------------
// Launch. Input order per metadata: x, conv1_w, conv1_b, conv2_w, conv2_b,
// centroids, assign_w, assign_b, lin_w, lin_b. Output: (32,7) float32.
// ---------------------------------------------------------------------------
extern "C" void kernel_launch(void* const* d_in, const int* in_sizes, int n_in,
                              void* d_out, int out_size)
{
    const float* x    = (const float*)d_in[0];
    const float* c1w  = (const float*)d_in[1];
    const float* c1b  = (const float*)d_in[2];
    const float* c2w  = (const float*)d_in[3];
    const float* c2b  = (const float*)d_in[4];
    const float* cent = (const float*)d_in[5];
    const float* aw   = (const float*)d_in[6];
    const float* ab   = (const float*)d_in[7];
    const float* lw   = (const float*)d_in[8];
    const float* lb   = (const float*)d_in[9];
    float* out = (float*)d_out;

    dim3 g1(1, 256, NIMG);
    conv1_pool_kernel<<<g1, 256>>>(x, c1w, c1b);

    dim3 g2(1, 128, NIMG);
    conv2_pool_kernel<<<g2, 128>>>(c2w, c2b);

    netvlad_partial_kernel<<<NIMG * NBLK, 128>>>(aw, ab);

    finalize_kernel<<<NIMG, 128>>>(cent, lw, lb, out);
}